// round 12
// baseline (speedup 1.0000x reference)
#include <cuda_runtime.h>
#include <math.h>

#define D      256
#define G3     768
#define MAXR   4096
#define NCB    96     // compute blocks (run alone on chip -> co-residency guaranteed)
#define NCHAIN 16     // blocks running the GEMV chain inside phase A

// ---------------- device scratch (static globals; no allocation) ----------------
__device__ float g_sub[D];
__device__ float g_gi0[G3];
__device__ float g_gh0[G3];
__device__ float g_gi[G3];
__device__ float g_gh[(size_t)MAXR * G3];
__device__ float g_rj[(size_t)MAXR * D];
__device__ float g_obj[(size_t)MAXR * D];
__device__ unsigned g_bcnt96, g_bgen96;   // 96-block barrier (self-resetting)
__device__ unsigned g_bcnt16, g_bgen16;   // 16-block chain barrier

// ---------------- helpers -------------------------------------------------------
__device__ __forceinline__ float dot8(float4 a0, float4 a1, float4 x0, float4 x1) {
    return a0.x*x0.x + a0.y*x0.y + a0.z*x0.z + a0.w*x0.w
         + a1.x*x1.x + a1.y*x1.y + a1.z*x1.z + a1.w*x1.w;
}
__device__ __forceinline__ float wred(float v) {
#pragma unroll
    for (int o = 16; o; o >>= 1) v += __shfl_xor_sync(0xffffffffu, v, o);
    return v;
}
__device__ __forceinline__ float sigf(float x) { return 1.f / (1.f + __expf(-x)); }

__device__ __forceinline__ unsigned long long pack2(float x, float y) {
    unsigned long long r;
    asm("mov.b64 %0, {%1, %2};" : "=l"(r) : "f"(x), "f"(y));
    return r;
}
__device__ __forceinline__ void unpack2(unsigned long long v, float& x, float& y) {
    asm("mov.b64 {%0, %1}, %2;" : "=f"(x), "=f"(y) : "l"(v));
}
__device__ __forceinline__ void ffma2(unsigned long long& d, unsigned long long a,
                                      unsigned long long b) {
    asm("fma.rn.f32x2 %0, %1, %2, %0;" : "+l"(d) : "l"(a), "l"(b));
}

// generic self-resetting group barrier (participants all resident by construction)
__device__ __forceinline__ void gbar(unsigned* cnt, unsigned* gen, unsigned n) {
    __syncthreads();
    if (threadIdx.x == 0) {
        __threadfence();
        unsigned my = *(volatile unsigned*)gen;
        if (atomicAdd(cnt, 1u) == n - 1u) {
            *(volatile unsigned*)cnt = 0;
            __threadfence();
            atomicAdd(gen, 1u);
        } else {
            while (*(volatile unsigned*)gen == my) { }
            __threadfence();
        }
    }
    __syncthreads();
}

// ---------------- in-kernel NT GEMM tile (f32x2 packed FMA), BM=64 --------------
template <int BN, int TN, bool TANH>
__device__ void tile_gemm(const float* __restrict__ A, const float* __restrict__ B,
                          const float* __restrict__ bias, float* __restrict__ C,
                          int M, int ldc, int K, int m0, int n0,
                          float (*As)[68], float (*Bs)[132]) {
    const int BM = 64, BK = 32, TM = 4;
    int tid = threadIdx.x;
    unsigned long long acc[TM][TN / 2];
#pragma unroll
    for (int i = 0; i < TM; i++)
#pragma unroll
        for (int j = 0; j < TN / 2; j++) acc[i][j] = 0ull;
    int tm = (tid & 15) * TM;
    int tn = (tid >> 4) * TN;

    for (int k0 = 0; k0 < K; k0 += BK) {
#pragma unroll
        for (int i = 0; i < (BM * BK) / (256 * 4); i++) {
            int idx = tid + i * 256;
            int row = idx >> 3, c4 = idx & 7;
            float4 v = make_float4(0.f, 0.f, 0.f, 0.f);
            if (m0 + row < M) v = *(const float4*)&A[(size_t)(m0 + row) * K + k0 + c4 * 4];
            As[c4 * 4 + 0][row] = v.x; As[c4 * 4 + 1][row] = v.y;
            As[c4 * 4 + 2][row] = v.z; As[c4 * 4 + 3][row] = v.w;
        }
#pragma unroll
        for (int i = 0; i < (BN * BK) / (256 * 4); i++) {
            int idx = tid + i * 256;
            int row = idx >> 3, c4 = idx & 7;
            float4 v = *(const float4*)&B[(size_t)(n0 + row) * K + k0 + c4 * 4];
            Bs[c4 * 4 + 0][row] = v.x; Bs[c4 * 4 + 1][row] = v.y;
            Bs[c4 * 4 + 2][row] = v.z; Bs[c4 * 4 + 3][row] = v.w;
        }
        __syncthreads();
#pragma unroll
        for (int k = 0; k < BK; k++) {
            float4 av = *(const float4*)&As[k][tm];
            unsigned long long pa[TM];
            pa[0] = pack2(av.x, av.x); pa[1] = pack2(av.y, av.y);
            pa[2] = pack2(av.z, av.z); pa[3] = pack2(av.w, av.w);
            unsigned long long pb[TN / 2];
#pragma unroll
            for (int j4 = 0; j4 < TN / 4; j4++) {
                float4 bv = *(const float4*)&Bs[k][tn + j4 * 4];
                pb[j4 * 2 + 0] = pack2(bv.x, bv.y);
                pb[j4 * 2 + 1] = pack2(bv.z, bv.w);
            }
#pragma unroll
            for (int i = 0; i < TM; i++)
#pragma unroll
                for (int j = 0; j < TN / 2; j++) ffma2(acc[i][j], pa[i], pb[j]);
        }
        __syncthreads();
    }
#pragma unroll
    for (int i = 0; i < TM; i++) {
        int m = m0 + tm + i;
        if (m < M) {
#pragma unroll
            for (int j = 0; j < TN / 2; j++) {
                float vx, vy; unpack2(acc[i][j], vx, vy);
                int n = n0 + tn + j * 2;
                if (bias) { vx += bias[n]; vy += bias[n + 1]; }
                if (TANH) { vx = tanhf(vx); vy = tanhf(vy); }
                C[(size_t)m * ldc + n]     = vx;
                C[(size_t)m * ldc + n + 1] = vy;
            }
        }
    }
}

// ---------------- compute mega-kernel (96 blocks, runs alone) -------------------
__global__ void __launch_bounds__(256)
compute_kernel(const float* __restrict__ sub_W, const float* __restrict__ W_ih,
               const float* __restrict__ W_hh,  const float* __restrict__ mask,
               const float* __restrict__ enc,   const float* __restrict__ sub_b,
               const float* __restrict__ b_ih,  const float* __restrict__ b_hh,
               const float* __restrict__ relT,  const float* __restrict__ obj_W,
               const float* __restrict__ obj_b, const int* __restrict__ seed_p,
               float* __restrict__ out, int R) {
    __shared__ float sAs[32][68];
    __shared__ float sBs[32][132];
    int t = threadIdx.x, w = t >> 5, l = t & 31, b = blockIdx.x;

    // ================= PHASE A: chain (blocks 0..15)  ||  gh GEMM (16..95) ======
    if (b < NCHAIN) {
        // p0: sub = tanh(sub_W@mask+sub_b) (+ seed row) ; gi0 = W_ih@enc+b_ih
#pragma unroll
        for (int it = 0; it < 8; it++) {
            int j = it * (NCHAIN * 8) + b * 8 + w;   // 0..1023
            const float4 *Wr, *x; float bias;
            if (j < 256) { Wr = (const float4*)(sub_W + (size_t)j * D); x = (const float4*)mask; bias = sub_b[j]; }
            else { Wr = (const float4*)(W_ih + (size_t)(j - 256) * D); x = (const float4*)enc; bias = b_ih[j - 256]; }
            float acc = wred(dot8(Wr[l], Wr[l + 32], __ldg(x + l), __ldg(x + l + 32)));
            if (l == 0) {
                acc += bias;
                if (j < 256) { float tt = tanhf(acc); g_sub[j] = tt; out[(size_t)seed_p[0] * D + j] = tt; }
                else g_gi0[j - 256] = acc;
            }
        }
        gbar(&g_bcnt16, &g_bgen16, NCHAIN);
        // p1: gh0 = W_hh @ sub + b_hh   (768 rows over 16 blocks)
#pragma unroll
        for (int it = 0; it < 6; it++) {
            int j = it * (NCHAIN * 8) + b * 8 + w;
            const float4* Wr = (const float4*)(W_hh + (size_t)j * D);
            const float4* x  = (const float4*)g_sub;
            float acc = wred(dot8(Wr[l], Wr[l + 32], x[l], x[l + 32]));
            if (l == 0) g_gh0[j] = acc + b_hh[j];
        }
        gbar(&g_bcnt16, &g_bgen16, NCHAIN);
        // p2: r0 (per-block smem) ; gi = W_ih @ r0 + b_ih
        {
            float* r0s = &sBs[0][0];
            float r = sigf(g_gi0[t] + g_gh0[t]);
            float z = sigf(g_gi0[D + t] + g_gh0[D + t]);
            float n = tanhf(g_gi0[2 * D + t] + r * g_gh0[2 * D + t]);
            r0s[t] = (1.f - z) * n + z * g_sub[t];
            __syncthreads();
#pragma unroll
            for (int it = 0; it < 6; it++) {
                int j = it * (NCHAIN * 8) + b * 8 + w;
                const float4* Wr = (const float4*)(W_ih + (size_t)j * D);
                const float4* x  = (const float4*)r0s;
                float acc = wred(dot8(Wr[l], Wr[l + 32], x[l], x[l + 32]));
                if (l == 0) g_gi[j] = acc + b_ih[j];
            }
        }
    } else {
        // gh = relT @ W_hh^T : 96 tiles of 64x128 over [R, 768]
        // blocks 16..95 take tile b-16; blocks 16..31 also take tile b-16+80.
        int tile = b - NCHAIN;
        tile_gemm<128, 8, false>(relT, W_hh, nullptr, g_gh, R, G3, D,
                                 (tile % 16) * 64, (tile / 16) * 128, sAs, sBs);
        tile += (NCB - NCHAIN);
        if (tile < 96) {
            tile_gemm<128, 8, false>(relT, W_hh, nullptr, g_gh, R, G3, D,
                                     (tile % 16) * 64, (tile / 16) * 128, sAs, sBs);
        }
    }
    gbar(&g_bcnt96, &g_bgen96, NCB);   // join: gi + gh both complete

    // ================= p4: rj per relation =====================================
    {
        float gi_r = g_gi[t], gi_z = g_gi[D + t], gi_n = g_gi[2 * D + t];
        float bh_r = b_hh[t], bh_z = b_hh[D + t], bh_n = b_hh[2 * D + t];
        for (int r = b; r < R; r += NCB) {
            const float* gh = g_gh + (size_t)r * G3;
            float rr = sigf(gi_r + gh[t] + bh_r);
            float z  = sigf(gi_z + gh[D + t] + bh_z);
            float n  = tanhf(gi_n + rr * (gh[2 * D + t] + bh_n));
            g_rj[(size_t)r * D + t] = (1.f - z) * n + z * relT[(size_t)r * D + t];
        }
    }
    gbar(&g_bcnt96, &g_bgen96, NCB);

    // ================= p5: obj = tanh(rj @ obj_W^T + obj_b) ====================
    if (b < 64)
        tile_gemm<64, 4, true>(g_rj, obj_W, obj_b, g_obj, R, D, D,
                               (b % 16) * 64, (b / 16) * 64, sAs, sBs);
}

// ---------------- unified scatter (unchanged: measured 66% DRAM) ----------------
__global__ void __launch_bounds__(256) scatter_kernel(
        const int* __restrict__ rel, const int* __restrict__ tail,
        const int* __restrict__ st,  const int* __restrict__ org,
        const float* __restrict__ entT, float* __restrict__ out, int E) {
    int l   = threadIdx.x & 31;
    int wid = (blockIdx.x * blockDim.x + threadIdx.x) >> 5;
    int nw  = (gridDim.x * blockDim.x) >> 5;
    int e   = wid * 2;
    int stride = nw * 2;
    for (; e + 1 < E; e += stride) {
        int s0 = st[e], s1 = st[e + 1];
        const float4* p0 = (s0 == 1)
            ? (const float4*)(entT + (size_t)org[e] * D)
            : (const float4*)(g_obj + (size_t)rel[e] * D);
        const float4* p1 = (s1 == 1)
            ? (const float4*)(entT + (size_t)org[e + 1] * D)
            : (const float4*)(g_obj + (size_t)rel[e + 1] * D);
        float4 a0 = __ldcs(p0 + l), a1 = __ldcs(p0 + l + 32);
        float4 b0 = __ldcs(p1 + l), b1 = __ldcs(p1 + l + 32);
        float4* d0 = (float4*)(out + (size_t)tail[e] * D);
        float4* d1 = (float4*)(out + (size_t)tail[e + 1] * D);
        __stcs(d0 + l, a0); __stcs(d0 + l + 32, a1);
        __stcs(d1 + l, b0); __stcs(d1 + l + 32, b1);
    }
    if (e < E) {
        int s0 = st[e];
        const float4* p0 = (s0 == 1)
            ? (const float4*)(entT + (size_t)org[e] * D)
            : (const float4*)(g_obj + (size_t)rel[e] * D);
        float4 a0 = __ldcs(p0 + l), a1 = __ldcs(p0 + l + 32);
        float4* d0 = (float4*)(out + (size_t)tail[e] * D);
        __stcs(d0 + l, a0); __stcs(d0 + l + 32, a1);
    }
}

// --------------------------------- launcher -------------------------------------
extern "C" void kernel_launch(void* const* d_in, const int* in_sizes, int n_in,
                              void* d_out, int out_size) {
    const float* encoder = (const float*)d_in[0];
    const float* mask    = (const float*)d_in[1];
    const float* entT    = (const float*)d_in[2];
    const float* relT    = (const float*)d_in[3];
    const float* W_ih    = (const float*)d_in[4];
    const float* W_hh    = (const float*)d_in[5];
    const float* b_ih    = (const float*)d_in[6];
    const float* b_hh    = (const float*)d_in[7];
    const float* sub_W   = (const float*)d_in[8];
    const float* sub_b   = (const float*)d_in[9];
    const float* obj_W   = (const float*)d_in[10];
    const float* obj_b   = (const float*)d_in[11];
    const int*   rel_ids = (const int*)d_in[12];
    const int*   tail_ids= (const int*)d_in[13];
    const int*   state   = (const int*)d_in[14];
    const int*   origin  = (const int*)d_in[15];
    const int*   seed_p  = (const int*)d_in[16];
    float* out = (float*)d_out;

    int E = in_sizes[12];
    int R = in_sizes[3] / D;
    if (R > MAXR) R = MAXR;

    // 1) fused compute: 96 blocks, runs alone -> barriers trivially safe.
    compute_kernel<<<NCB, 256>>>(sub_W, W_ih, W_hh, mask, encoder, sub_b,
                                 b_ih, b_hh, relT, obj_W, obj_b, seed_p, out, R);

    // 2) unified scatter at full occupancy (measured near-roofline).
    scatter_kernel<<<1480, 256>>>(rel_ids, tail_ids, state, origin, entT, out, E);
}

// round 14
// speedup vs baseline: 1.6731x; 1.6731x over previous
#include <cuda_runtime.h>
#include <math.h>

#define D    256
#define G3   768
#define MAXR 4096
#define NBK  444     // total blocks = 148 SMs * 3 (all wave-1 resident)
#define NCB  96      // compute blocks (barrier participants)
#define CH   16      // edges per cursor grab

// ---------------- device scratch (static globals; no allocation) ----------------
__device__ float g_sub[D];
__device__ float g_gi0[G3];
__device__ float g_gh0[G3];
__device__ float g_gi[G3];
__device__ float g_gh[(size_t)MAXR * G3];
__device__ float g_rj[(size_t)MAXR * D];
__device__ float g_obj[(size_t)MAXR * D];
__device__ unsigned g_bcnt;     // 96-block barrier counter (self-resetting)
__device__ unsigned g_bgen;     // barrier generation (monotonic across replays)
__device__ unsigned g_cdone;    // obj-table completion count (target 64)
__device__ unsigned g_cur_ent;  // ent-edge work cursor
__device__ unsigned g_cur_obj;  // obj-edge work cursor
__device__ unsigned g_ack;      // end-of-kernel reset ack (target NBK)

// ---------------- helpers -------------------------------------------------------
__device__ __forceinline__ float dot8(float4 a0, float4 a1, float4 x0, float4 x1) {
    return a0.x*x0.x + a0.y*x0.y + a0.z*x0.z + a0.w*x0.w
         + a1.x*x1.x + a1.y*x1.y + a1.z*x1.z + a1.w*x1.w;
}
__device__ __forceinline__ float wred(float v) {
#pragma unroll
    for (int o = 16; o; o >>= 1) v += __shfl_xor_sync(0xffffffffu, v, o);
    return v;
}
__device__ __forceinline__ float sigf(float x) { return 1.f / (1.f + __expf(-x)); }

__device__ __forceinline__ unsigned long long pack2(float x, float y) {
    unsigned long long r;
    asm("mov.b64 %0, {%1, %2};" : "=l"(r) : "f"(x), "f"(y));
    return r;
}
__device__ __forceinline__ void unpack2(unsigned long long v, float& x, float& y) {
    asm("mov.b64 {%0, %1}, %2;" : "=f"(x), "=f"(y) : "l"(v));
}
__device__ __forceinline__ void ffma2(unsigned long long& d, unsigned long long a,
                                      unsigned long long b) {
    asm("fma.rn.f32x2 %0, %1, %2, %0;" : "+l"(d) : "l"(a), "l"(b));
}

// barrier among the NCB compute blocks (all guaranteed wave-1 resident)
__device__ __forceinline__ void bar96() {
    __syncthreads();
    if (threadIdx.x == 0) {
        __threadfence();
        unsigned my = *(volatile unsigned*)&g_bgen;
        if (atomicAdd(&g_bcnt, 1u) == (unsigned)(NCB - 1)) {
            *(volatile unsigned*)&g_bcnt = 0;
            __threadfence();
            atomicAdd(&g_bgen, 1u);
        } else {
            while (*(volatile unsigned*)&g_bgen == my) { }
            __threadfence();
        }
    }
    __syncthreads();
}

// ---------------- in-kernel NT GEMM tile (f32x2 packed FMA) ---------------------
template <int BN, int TN, bool TANH>
__device__ void tile_gemm(const float* __restrict__ A, const float* __restrict__ B,
                          const float* __restrict__ bias, float* __restrict__ C,
                          int M, int ldc, int K, int m0, int n0,
                          float (*As)[68], float (*Bs)[132]) {
    const int BM = 64, BK = 32, TM = 4;
    int tid = threadIdx.x;
    unsigned long long acc[TM][TN / 2];
#pragma unroll
    for (int i = 0; i < TM; i++)
#pragma unroll
        for (int j = 0; j < TN / 2; j++) acc[i][j] = 0ull;
    int tm = (tid & 15) * TM;
    int tn = (tid >> 4) * TN;

    for (int k0 = 0; k0 < K; k0 += BK) {
#pragma unroll
        for (int i = 0; i < (BM * BK) / (256 * 4); i++) {
            int idx = tid + i * 256;
            int row = idx >> 3, c4 = idx & 7;
            float4 v = make_float4(0.f, 0.f, 0.f, 0.f);
            if (m0 + row < M) v = *(const float4*)&A[(size_t)(m0 + row) * K + k0 + c4 * 4];
            As[c4 * 4 + 0][row] = v.x; As[c4 * 4 + 1][row] = v.y;
            As[c4 * 4 + 2][row] = v.z; As[c4 * 4 + 3][row] = v.w;
        }
#pragma unroll
        for (int i = 0; i < (BN * BK) / (256 * 4); i++) {
            int idx = tid + i * 256;
            int row = idx >> 3, c4 = idx & 7;
            float4 v = *(const float4*)&B[(size_t)(n0 + row) * K + k0 + c4 * 4];
            Bs[c4 * 4 + 0][row] = v.x; Bs[c4 * 4 + 1][row] = v.y;
            Bs[c4 * 4 + 2][row] = v.z; Bs[c4 * 4 + 3][row] = v.w;
        }
        __syncthreads();
#pragma unroll
        for (int k = 0; k < BK; k++) {
            float4 av = *(const float4*)&As[k][tm];
            unsigned long long pa[TM];
            pa[0] = pack2(av.x, av.x); pa[1] = pack2(av.y, av.y);
            pa[2] = pack2(av.z, av.z); pa[3] = pack2(av.w, av.w);
            unsigned long long pb[TN / 2];
#pragma unroll
            for (int j4 = 0; j4 < TN / 4; j4++) {
                float4 bv = *(const float4*)&Bs[k][tn + j4 * 4];
                pb[j4 * 2 + 0] = pack2(bv.x, bv.y);
                pb[j4 * 2 + 1] = pack2(bv.z, bv.w);
            }
#pragma unroll
            for (int i = 0; i < TM; i++)
#pragma unroll
                for (int j = 0; j < TN / 2; j++) ffma2(acc[i][j], pa[i], pb[j]);
        }
        __syncthreads();
    }
#pragma unroll
    for (int i = 0; i < TM; i++) {
        int m = m0 + tm + i;
        if (m < M) {
#pragma unroll
            for (int j = 0; j < TN / 2; j++) {
                float vx, vy; unpack2(acc[i][j], vx, vy);
                int n = n0 + tn + j * 2;
                if (bias) { vx += bias[n]; vy += bias[n + 1]; }
                if (TANH) { vx = tanhf(vx); vy = tanhf(vy); }
                C[(size_t)m * ldc + n]     = vx;
                C[(size_t)m * ldc + n + 1] = vy;
            }
        }
    }
}

// ---------------- the ONE kernel ------------------------------------------------
__global__ void __launch_bounds__(256, 3)
fused_kernel(const float* __restrict__ sub_W, const float* __restrict__ W_ih,
             const float* __restrict__ W_hh,  const float* __restrict__ mask,
             const float* __restrict__ enc,   const float* __restrict__ sub_b,
             const float* __restrict__ b_ih,  const float* __restrict__ b_hh,
             const float* __restrict__ relT,  const float* __restrict__ obj_W,
             const float* __restrict__ obj_b, const float* __restrict__ entT,
             const int* __restrict__ rel_ids, const int* __restrict__ tail_ids,
             const int* __restrict__ st,      const int* __restrict__ org,
             const int* __restrict__ seed_p,  float* __restrict__ out,
             int R, int E) {
    __shared__ float sAs[32][68];
    __shared__ float sBs[32][132];
    int t = threadIdx.x, w = t >> 5, l = t & 31, b = blockIdx.x;

    if (b < NCB) {
        // ===================== compute phases (96 blocks) =====================
        // p0: sub = tanh(sub_W@mask+sub_b) (+ seed row) ; gi0 = W_ih@enc+b_ih
#pragma unroll
        for (int it = 0; it < 2; it++) {
            int j = it * (NCB * 8) + b * 8 + w;
            if (j < 1024) {
                const float4 *Wr, *x; float bias;
                if (j < 256) { Wr = (const float4*)(sub_W + (size_t)j * D); x = (const float4*)mask; bias = sub_b[j]; }
                else { Wr = (const float4*)(W_ih + (size_t)(j - 256) * D); x = (const float4*)enc; bias = b_ih[j - 256]; }
                float acc = wred(dot8(Wr[l], Wr[l + 32], __ldg(x + l), __ldg(x + l + 32)));
                if (l == 0) {
                    acc += bias;
                    if (j < 256) { float tt = tanhf(acc); g_sub[j] = tt; out[(size_t)seed_p[0] * D + j] = tt; }
                    else g_gi0[j - 256] = acc;
                }
            }
        }
        bar96();
        // p1: gh0 = W_hh @ sub + b_hh
        {
            int j = b * 8 + w;
            const float4* Wr = (const float4*)(W_hh + (size_t)j * D);
            const float4* x  = (const float4*)g_sub;
            float acc = wred(dot8(Wr[l], Wr[l + 32], x[l], x[l + 32]));
            if (l == 0) g_gh0[j] = acc + b_hh[j];
        }
        bar96();
        // p2: r0 (per-block smem) ; gi = W_ih @ r0 + b_ih
        {
            float* r0s = &sBs[0][0];
            float r = sigf(g_gi0[t] + g_gh0[t]);
            float z = sigf(g_gi0[D + t] + g_gh0[D + t]);
            float n = tanhf(g_gi0[2 * D + t] + r * g_gh0[2 * D + t]);
            r0s[t] = (1.f - z) * n + z * g_sub[t];
            __syncthreads();
            int j = b * 8 + w;
            const float4* Wr = (const float4*)(W_ih + (size_t)j * D);
            const float4* x  = (const float4*)r0s;
            float acc = wred(dot8(Wr[l], Wr[l + 32], x[l], x[l + 32]));
            if (l == 0) g_gi[j] = acc + b_ih[j];
        }
        bar96();
        // p3: gh = relT @ W_hh^T  (96 tiles of 64x128 over [R, 768])
        tile_gemm<128, 8, false>(relT, W_hh, nullptr, g_gh, R, G3, D,
                                 (b % 16) * 64, (b / 16) * 128, sAs, sBs);
        bar96();
        // p4: rj per relation
        {
            float gi_r = g_gi[t], gi_z = g_gi[D + t], gi_n = g_gi[2 * D + t];
            float bh_r = b_hh[t], bh_z = b_hh[D + t], bh_n = b_hh[2 * D + t];
            for (int r = b; r < R; r += NCB) {
                const float* gh = g_gh + (size_t)r * G3;
                float rr = sigf(gi_r + gh[t] + bh_r);
                float z  = sigf(gi_z + gh[D + t] + bh_z);
                float n  = tanhf(gi_n + rr * (gh[2 * D + t] + bh_n));
                g_rj[(size_t)r * D + t] = (1.f - z) * n + z * relT[(size_t)r * D + t];
            }
        }
        bar96();
        // p5: obj = tanh(rj @ obj_W^T + obj_b) on blocks 0..63; each signals done.
        if (b < 64) {
            tile_gemm<64, 4, true>(g_rj, obj_W, obj_b, g_obj, R, D, D,
                                   (b % 16) * 64, (b / 16) * 64, sAs, sBs);
            __syncthreads();
            if (t == 0) { __threadfence(); atomicAdd(&g_cdone, 1u); }
        }
        // fall through: compute blocks join the scatters
    }

    // ===================== ent scatter (dynamic cursor, 4-edge unroll) ========
    for (;;) {
        unsigned base;
        if (l == 0) base = atomicAdd(&g_cur_ent, (unsigned)CH);
        base = __shfl_sync(0xffffffffu, base, 0);
        if (base >= (unsigned)E) break;
        unsigned end = base + CH; if (end > (unsigned)E) end = E;
        unsigned e = base;
        for (; e + 3 < end; e += 4) {
            int s0 = st[e], s1 = st[e + 1], s2 = st[e + 2], s3 = st[e + 3];
            bool d0 = (s0 == 1), d1 = (s1 == 1), d2 = (s2 == 1), d3 = (s3 == 1);
            float4 a0, a1, b0, b1, c0, c1, f0, f1;
            if (d0) { const float4* p = (const float4*)(entT + (size_t)org[e] * D);
                      a0 = __ldcs(p + l); a1 = __ldcs(p + l + 32); }
            if (d1) { const float4* p = (const float4*)(entT + (size_t)org[e + 1] * D);
                      b0 = __ldcs(p + l); b1 = __ldcs(p + l + 32); }
            if (d2) { const float4* p = (const float4*)(entT + (size_t)org[e + 2] * D);
                      c0 = __ldcs(p + l); c1 = __ldcs(p + l + 32); }
            if (d3) { const float4* p = (const float4*)(entT + (size_t)org[e + 3] * D);
                      f0 = __ldcs(p + l); f1 = __ldcs(p + l + 32); }
            if (d0) { float4* d = (float4*)(out + (size_t)tail_ids[e] * D);
                      __stcs(d + l, a0); __stcs(d + l + 32, a1); }
            if (d1) { float4* d = (float4*)(out + (size_t)tail_ids[e + 1] * D);
                      __stcs(d + l, b0); __stcs(d + l + 32, b1); }
            if (d2) { float4* d = (float4*)(out + (size_t)tail_ids[e + 2] * D);
                      __stcs(d + l, c0); __stcs(d + l + 32, c1); }
            if (d3) { float4* d = (float4*)(out + (size_t)tail_ids[e + 3] * D);
                      __stcs(d + l, f0); __stcs(d + l + 32, f1); }
        }
        for (; e < end; e++) {
            if (st[e] == 1) {
                const float4* s = (const float4*)(entT + (size_t)org[e] * D);
                float4* d = (float4*)(out + (size_t)tail_ids[e] * D);
                float4 v0 = __ldcs(s + l), v1 = __ldcs(s + l + 32);
                __stcs(d + l, v0); __stcs(d + l + 32, v1);
            }
        }
    }

    // ===================== wait for obj table, then obj scatter =============
    if (t == 0) { while (*(volatile unsigned*)&g_cdone < 64u) { } }
    __syncthreads();
    __threadfence();
    for (;;) {
        unsigned base;
        if (l == 0) base = atomicAdd(&g_cur_obj, (unsigned)CH);
        base = __shfl_sync(0xffffffffu, base, 0);
        if (base >= (unsigned)E) break;
        unsigned end = base + CH; if (end > (unsigned)E) end = E;
        unsigned e = base;
        for (; e + 3 < end; e += 4) {
            int s0 = st[e], s1 = st[e + 1], s2 = st[e + 2], s3 = st[e + 3];
            bool d0 = (s0 != 1), d1 = (s1 != 1), d2 = (s2 != 1), d3 = (s3 != 1);
            float4 a0, a1, b0, b1, c0, c1, f0, f1;
            if (d0) { const float4* p = (const float4*)(g_obj + (size_t)rel_ids[e] * D);
                      a0 = __ldg(p + l); a1 = __ldg(p + l + 32); }
            if (d1) { const float4* p = (const float4*)(g_obj + (size_t)rel_ids[e + 1] * D);
                      b0 = __ldg(p + l); b1 = __ldg(p + l + 32); }
            if (d2) { const float4* p = (const float4*)(g_obj + (size_t)rel_ids[e + 2] * D);
                      c0 = __ldg(p + l); c1 = __ldg(p + l + 32); }
            if (d3) { const float4* p = (const float4*)(g_obj + (size_t)rel_ids[e + 3] * D);
                      f0 = __ldg(p + l); f1 = __ldg(p + l + 32); }
            if (d0) { float4* d = (float4*)(out + (size_t)tail_ids[e] * D);
                      __stcs(d + l, a0); __stcs(d + l + 32, a1); }
            if (d1) { float4* d = (float4*)(out + (size_t)tail_ids[e + 1] * D);
                      __stcs(d + l, b0); __stcs(d + l + 32, b1); }
            if (d2) { float4* d = (float4*)(out + (size_t)tail_ids[e + 2] * D);
                      __stcs(d + l, c0); __stcs(d + l + 32, c1); }
            if (d3) { float4* d = (float4*)(out + (size_t)tail_ids[e + 3] * D);
                      __stcs(d + l, f0); __stcs(d + l + 32, f1); }
        }
        for (; e < end; e++) {
            if (st[e] != 1) {
                const float4* s = (const float4*)(g_obj + (size_t)rel_ids[e] * D);
                float4* d = (float4*)(out + (size_t)tail_ids[e] * D);
                float4 v0 = __ldg(s + l), v1 = __ldg(s + l + 32);
                __stcs(d + l, v0); __stcs(d + l + 32, v1);
            }
        }
    }

    // ===================== reset shared state for next graph replay =========
    __syncthreads();
    if (t == 0) {
        if (atomicAdd(&g_ack, 1u) == (unsigned)(NBK - 1)) {
            g_cdone = 0u; g_cur_ent = 0u; g_cur_obj = 0u;
            __threadfence();
            *(volatile unsigned*)&g_ack = 0u;
        }
    }
}

// --------------------------------- launcher -------------------------------------
extern "C" void kernel_launch(void* const* d_in, const int* in_sizes, int n_in,
                              void* d_out, int out_size) {
    const float* encoder = (const float*)d_in[0];
    const float* mask    = (const float*)d_in[1];
    const float* entT    = (const float*)d_in[2];
    const float* relT    = (const float*)d_in[3];
    const float* W_ih    = (const float*)d_in[4];
    const float* W_hh    = (const float*)d_in[5];
    const float* b_ih    = (const float*)d_in[6];
    const float* b_hh    = (const float*)d_in[7];
    const float* sub_W   = (const float*)d_in[8];
    const float* sub_b   = (const float*)d_in[9];
    const float* obj_W   = (const float*)d_in[10];
    const float* obj_b   = (const float*)d_in[11];
    const int*   rel_ids = (const int*)d_in[12];
    const int*   tail_ids= (const int*)d_in[13];
    const int*   state   = (const int*)d_in[14];
    const int*   origin  = (const int*)d_in[15];
    const int*   seed_p  = (const int*)d_in[16];
    float* out = (float*)d_out;

    int E = in_sizes[12];
    int R = in_sizes[3] / D;
    if (R > MAXR) R = MAXR;

    fused_kernel<<<NBK, 256>>>(sub_W, W_ih, W_hh, mask, encoder, sub_b, b_ih, b_hh,
                               relT, obj_W, obj_b, entT,
                               rel_ids, tail_ids, state, origin, seed_p, out, R, E);
}